// round 7
// baseline (speedup 1.0000x reference)
#include <cuda_runtime.h>
#include <cuda_bf16.h>
#include <math.h>
#include <stdint.h>

#define N_     256
#define M_     50000
#define K_     3072
#define KT     32             // bf16 k per tile
#define NT1    (K_ / KT)      // 96
#define NTILE  391            // ceil(M/128)
#define INV_VAR 4.0f
#define HMAX   64
#define THRESH 30.0f
#define STG    49152          // stage: Ahi 8K | Alo 8K | Bhi 16K | Blo 16K

// ---------------- device scratch (allocation-free) ----------------
__device__ __align__(128) float          g_scores[(size_t)M_ * N_];
__device__ __align__(128) __nv_bfloat16  g_Xhi[(size_t)N_ * K_];
__device__ __align__(128) __nv_bfloat16  g_Xlo[(size_t)N_ * K_];
__device__ __align__(128) float          g_tmax[(size_t)NTILE * N_];
__device__ unsigned int g_gmax_u[N_];
__device__ int          g_cnt[N_];
__device__ int          g_hit_m[N_ * HMAX];
__device__ float        g_hit_s[N_ * HMAX];

// ---------------- helpers ----------------
__device__ __forceinline__ uint32_t s2u(const void* p) {
    return (uint32_t)__cvta_generic_to_shared(p);
}
// tile rows of 32 bf16 (64B); two logical rows per 128B phys row, XOR swizzle.
__device__ __forceinline__ uint32_t soff(uint32_t r, uint32_t c) {
    return (((r >> 1) << 3) + ((((r & 1) << 2) | c) ^ ((r >> 1) & 7))) << 4;
}
__device__ __forceinline__ void cp16(uint32_t dst, const void* src) {
    asm volatile("cp.async.cg.shared.global [%0], [%1], 16;" :: "r"(dst), "l"(src));
}
__device__ __forceinline__ void cp_commit() { asm volatile("cp.async.commit_group;"); }
__device__ __forceinline__ void cp_wait0() { asm volatile("cp.async.wait_group 0;" ::: "memory"); }

__device__ __forceinline__ void ldsm4(uint32_t* d, uint32_t addr) {
    asm volatile("ldmatrix.sync.aligned.m8n8.x4.shared.b16 {%0,%1,%2,%3}, [%4];"
        : "=r"(d[0]), "=r"(d[1]), "=r"(d[2]), "=r"(d[3]) : "r"(addr));
}
__device__ __forceinline__ void mma_bf16(float* c, const uint32_t* a, uint32_t b0, uint32_t b1) {
    asm volatile("mma.sync.aligned.m16n8k16.row.col.f32.bf16.bf16.f32 "
        "{%0,%1,%2,%3}, {%4,%5,%6,%7}, {%8,%9}, {%0,%1,%2,%3};"
        : "+f"(c[0]), "+f"(c[1]), "+f"(c[2]), "+f"(c[3])
        : "r"(a[0]), "r"(a[1]), "r"(a[2]), "r"(a[3]), "r"(b0), "r"(b1));
}
__device__ __forceinline__ unsigned int fkey(float f) {
    unsigned int b = __float_as_uint(f);
    return (b & 0x80000000u) ? ~b : (b | 0x80000000u);
}
__device__ __forceinline__ float funkey(unsigned int k) {
    unsigned int b = (k & 0x80000000u) ? (k & 0x7FFFFFFFu) : ~k;
    return __uint_as_float(b);
}
__device__ __forceinline__ uint32_t pk2(float x, float y) {   // bf16(x) low, bf16(y) high
    __nv_bfloat162 t = __floats2bfloat162_rn(x, y);
    return *(uint32_t*)&t;
}

// ---------------- zero per-launch state ----------------
__global__ void k_zero() {
    const int t = threadIdx.x;
    g_gmax_u[t] = 0u;
    g_cnt[t] = 0;
}

// ---------------- X fp32 -> (bf16 hi, lo), tiny ----------------
__global__ __launch_bounds__(256)
void k_split_x(const float* __restrict__ X) {
    size_t i = (size_t)blockIdx.x * 256 + threadIdx.x;
    if (i >= (size_t)N_ * K_ / 4) return;
    float4 v = ((const float4*)X)[i];
    float vv[4] = {v.x, v.y, v.z, v.w};
    unsigned long long ph = 0, pl = 0;
    #pragma unroll
    for (int c = 0; c < 4; c++) {
        __nv_bfloat16 h = __float2bfloat16(vv[c]);
        __nv_bfloat16 l = __float2bfloat16(vv[c] - __bfloat162float(h));
        ph |= (unsigned long long)(*(unsigned short*)&h) << (16 * c);
        pl |= (unsigned long long)(*(unsigned short*)&l) << (16 * c);
    }
    ((unsigned long long*)g_Xhi)[i] = ph;
    ((unsigned long long*)g_Xlo)[i] = pl;
}

// ---------------- GEMM1: scores[m][n] = 4 * D.X^T, 3-term split bf16 ----------
// CTA tile 128m x 256n, grid.y == 1 (D read exactly once, as fp32, split fused
// in-kernel). 8 warps = 2m x 4n, warp tile 64x64. Single __syncthreads per tile.
// Epilogue stores scores, per-(CTA,n) tile max, and global per-n max.
__global__ __launch_bounds__(256, 1)
void k_gemm1(const float* __restrict__ Dp) {
    extern __shared__ char smem[];
    const uint32_t sb = s2u(smem);
    const int tid = threadIdx.x, wid = tid >> 5, lane = tid & 31;
    const int m0 = blockIdx.x * 128;
    const int wm = (wid >> 2) * 64;        // 0 or 64
    const int wn = (wid & 3) * 64;         // 0,64,128,192

    int arow = m0 + (tid >> 1); if (arow >= M_) arow = M_ - 1;
    const float* aptr = Dp + (size_t)arow * K_ + (tid & 1) * 16;
    const uint32_t a_off  = soff(tid >> 1, (tid & 1) * 2);
    const uint32_t a_off2 = soff(tid >> 1, (tid & 1) * 2 + 1);

    float acc[4][8][4];
    #pragma unroll
    for (int a = 0; a < 4; a++)
        #pragma unroll
        for (int b = 0; b < 8; b++)
            #pragma unroll
            for (int q = 0; q < 4; q++) acc[a][b][q] = 0.f;

    float4 fA[4];
    auto ldgA = [&](int kt) {
        const float* p = aptr + kt * KT;
        fA[0] = *(const float4*)(p);
        fA[1] = *(const float4*)(p + 4);
        fA[2] = *(const float4*)(p + 8);
        fA[3] = *(const float4*)(p + 12);
    };
    auto stsA = [&](int s) {
        char* st = smem + s * STG;
        #pragma unroll
        for (int c2 = 0; c2 < 2; c2++) {
            float4 a = fA[2 * c2], b = fA[2 * c2 + 1];
            uint4 hi, lo;
            hi.x = pk2(a.x, a.y); hi.y = pk2(a.z, a.w);
            hi.z = pk2(b.x, b.y); hi.w = pk2(b.z, b.w);
            __nv_bfloat162 h0 = *(__nv_bfloat162*)&hi.x, h1 = *(__nv_bfloat162*)&hi.y;
            __nv_bfloat162 h2 = *(__nv_bfloat162*)&hi.z, h3 = *(__nv_bfloat162*)&hi.w;
            lo.x = pk2(a.x - __bfloat162float(h0.x), a.y - __bfloat162float(h0.y));
            lo.y = pk2(a.z - __bfloat162float(h1.x), a.w - __bfloat162float(h1.y));
            lo.z = pk2(b.x - __bfloat162float(h2.x), b.y - __bfloat162float(h2.y));
            lo.w = pk2(b.z - __bfloat162float(h3.x), b.w - __bfloat162float(h3.y));
            uint32_t off = c2 ? a_off2 : a_off;
            *(uint4*)(st + off)        = hi;
            *(uint4*)(st + 8192 + off) = lo;
        }
    };
    auto cpB = [&](int s, int kt) {
        const uint32_t st = sb + s * STG;
        const int k0 = kt * KT;
        #pragma unroll
        for (int q = 0; q < 4; q++) {
            int e = q * 256 + tid;
            int r = e >> 2, c = e & 3;
            uint32_t off = soff(r, c);
            size_t gb = (size_t)r * K_ + k0 + c * 8;
            cp16(st + 16384 + off, g_Xhi + gb);
            cp16(st + 32768 + off, g_Xlo + gb);
        }
        cp_commit();
    };

    ldgA(0);
    cpB(0, 0);
    stsA(0);

    for (int t = 0; t < NT1; t++) {
        cp_wait0();
        __syncthreads();
        const bool pf = (t + 1 < NT1);
        if (pf) { ldgA(t + 1); cpB((t + 1) & 1, t + 1); }

        const uint32_t st = sb + (t & 1) * STG;
        #pragma unroll
        for (int ks = 0; ks < 2; ks++) {
            const uint32_t cc = ks * 2 + (lane >> 4);
            uint32_t ah[4][4], al[4][4];
            #pragma unroll
            for (int mi = 0; mi < 4; mi++) {
                uint32_t a = st + soff(wm + mi * 16 + (lane & 15), cc);
                ldsm4(ah[mi], a);
                ldsm4(al[mi], a + 8192);
            }
            #pragma unroll
            for (int g = 0; g < 4; g++) {
                uint32_t bh[4], bl[4];
                uint32_t a = st + 16384 + soff(wn + g * 16 + (lane & 15), cc);
                ldsm4(bh, a);
                ldsm4(bl, a + 16384);
                #pragma unroll
                for (int mi = 0; mi < 4; mi++) {
                    mma_bf16(acc[mi][g*2],   ah[mi], bh[0], bh[2]);
                    mma_bf16(acc[mi][g*2+1], ah[mi], bh[1], bh[3]);
                    mma_bf16(acc[mi][g*2],   ah[mi], bl[0], bl[2]);
                    mma_bf16(acc[mi][g*2+1], ah[mi], bl[1], bl[3]);
                    mma_bf16(acc[mi][g*2],   al[mi], bh[0], bh[2]);
                    mma_bf16(acc[mi][g*2+1], al[mi], bh[1], bh[3]);
                }
            }
        }
        if (pf) stsA((t + 1) & 1);
    }

    // epilogue: scale, store scores, per-n warp maxima
    float mv0[8], mv1[8];
    #pragma unroll
    for (int mi = 0; mi < 4; mi++) {
        int m = m0 + wm + mi * 16 + (lane >> 2);
        #pragma unroll
        for (int nj = 0; nj < 8; nj++) {
            int n = wn + nj * 8 + (lane & 3) * 2;
            float v0 = acc[mi][nj][0] * INV_VAR, v1 = acc[mi][nj][1] * INV_VAR;
            float v2 = acc[mi][nj][2] * INV_VAR, v3 = acc[mi][nj][3] * INV_VAR;
            acc[mi][nj][0] = v0; acc[mi][nj][1] = v1;
            acc[mi][nj][2] = v2; acc[mi][nj][3] = v3;
            if (m < M_)     *(float2*)&g_scores[(size_t)m * N_ + n]       = make_float2(v0, v1);
            if (m + 8 < M_) *(float2*)&g_scores[(size_t)(m + 8) * N_ + n] = make_float2(v2, v3);
        }
    }
    #pragma unroll
    for (int nj = 0; nj < 8; nj++) {
        float v0 = -1e30f, v1 = -1e30f;
        #pragma unroll
        for (int mi = 0; mi < 4; mi++) {
            v0 = fmaxf(v0, fmaxf(acc[mi][nj][0], acc[mi][nj][2]));
            v1 = fmaxf(v1, fmaxf(acc[mi][nj][1], acc[mi][nj][3]));
        }
        #pragma unroll
        for (int mk = 4; mk < 32; mk <<= 1) {
            v0 = fmaxf(v0, __shfl_xor_sync(0xFFFFFFFFu, v0, mk));
            v1 = fmaxf(v1, __shfl_xor_sync(0xFFFFFFFFu, v1, mk));
        }
        mv0[nj] = v0; mv1[nj] = v1;
    }
    // combine the two m-warps per n (smem stage-0 region is dead: last read
    // was tile NT1-2, ordered before the final top-of-loop barrier)
    float* s_max = (float*)smem;          // 256 floats
    __syncthreads();
    if (wm == 0 && (lane >> 2) == 0) {
        #pragma unroll
        for (int nj = 0; nj < 8; nj++) {
            int n = wn + nj * 8 + (lane & 3) * 2;
            s_max[n] = mv0[nj]; s_max[n + 1] = mv1[nj];
        }
    }
    __syncthreads();
    if (wm == 64 && (lane >> 2) == 0) {
        #pragma unroll
        for (int nj = 0; nj < 8; nj++) {
            int n = wn + nj * 8 + (lane & 3) * 2;
            float c0 = fmaxf(mv0[nj], s_max[n]);
            float c1 = fmaxf(mv1[nj], s_max[n + 1]);
            g_tmax[(size_t)blockIdx.x * N_ + n]     = c0;
            g_tmax[(size_t)blockIdx.x * N_ + n + 1] = c1;
            atomicMax(&g_gmax_u[n],     fkey(c0));
            atomicMax(&g_gmax_u[n + 1], fkey(c1));
        }
    }
}

// ---------------- select: scan tile maxima, descend only into hot tiles -----
__global__ __launch_bounds__(128)
void k_select() {
    __shared__ int s_cnt;
    const int n = blockIdx.x;
    if (threadIdx.x == 0) s_cnt = 0;
    __syncthreads();
    const float thr = funkey(g_gmax_u[n]) - THRESH;
    for (int b = threadIdx.x; b < NTILE; b += 128) {
        if (g_tmax[(size_t)b * N_ + n] > thr) {
            int mb = b * 128;
            int me = mb + 128; if (me > M_) me = M_;
            for (int m = mb; m < me; m++) {
                float v = g_scores[(size_t)m * N_ + n];
                if (v > thr) {
                    int s = atomicAdd(&s_cnt, 1);
                    if (s < HMAX) {
                        g_hit_m[n * HMAX + s] = m;
                        g_hit_s[n * HMAX + s] = v;
                    }
                }
            }
        }
    }
    __syncthreads();
    if (threadIdx.x == 0) g_cnt[n] = s_cnt;
}

// ---------------- out[n][:] = sum_l w_l D[m_l][:] / sum_l w_l  (exact fp32) --
__global__ __launch_bounds__(256)
void k_out(const float* __restrict__ D, float* __restrict__ out) {
    __shared__ int   hm[HMAX];
    __shared__ float hs[HMAX];
    __shared__ float hw[HMAX];
    const int n = blockIdx.x, tid = threadIdx.x;
    int cnt = g_cnt[n]; if (cnt > HMAX) cnt = HMAX;
    if (tid < cnt) { hm[tid] = g_hit_m[n * HMAX + tid]; hs[tid] = g_hit_s[n * HMAX + tid]; }
    __syncthreads();
    if (tid == 0) {            // sort by m -> deterministic accumulation order
        for (int i = 1; i < cnt; i++) {
            int km = hm[i]; float ks_ = hs[i]; int j = i - 1;
            while (j >= 0 && hm[j] > km) { hm[j+1] = hm[j]; hs[j+1] = hs[j]; j--; }
            hm[j+1] = km; hs[j+1] = ks_;
        }
    }
    __syncthreads();
    const float gm = funkey(g_gmax_u[n]);
    if (tid < cnt) hw[tid] = expf(hs[tid] - gm);
    __syncthreads();
    float wsum = 0.f;
    for (int l = 0; l < cnt; l++) wsum += hw[l];
    const float inv = 1.0f / wsum;
    for (int j = tid; j < K_; j += 256) {
        float a = 0.f;
        for (int l = 0; l < cnt; l++)
            a += hw[l] * D[(size_t)hm[l] * K_ + j];
        out[(size_t)n * K_ + j] = a * inv;
    }
}

// ---------------- launch ----------------
extern "C" void kernel_launch(void* const* d_in, const int* in_sizes, int n_in,
                              void* d_out, int out_size) {
    (void)in_sizes; (void)n_in; (void)out_size;
    const float* X = (const float*)d_in[0];
    const float* D = (const float*)d_in[1];
    float* out = (float*)d_out;

    cudaFuncSetAttribute(k_gemm1, cudaFuncAttributeMaxDynamicSharedMemorySize, 2 * STG);

    k_zero<<<1, 256>>>();
    k_split_x<<<(N_ * K_ / 4 + 255) / 256, 256>>>(X);

    k_gemm1<<<(M_ + 127) / 128, 256, 2 * STG>>>(D);

    k_select<<<N_, 128>>>();
    k_out<<<N_, 256>>>(D, out);
}

// round 8
// speedup vs baseline: 1.1871x; 1.1871x over previous
#include <cuda_runtime.h>
#include <cuda_bf16.h>
#include <math.h>
#include <stdint.h>

#define N_     256
#define M_     50000
#define K_     3072
#define KT     32             // bf16 k per tile
#define NT1    (K_ / KT)      // 96
#define NTILE  391            // ceil(M/128)
#define INV_VAR 4.0f
#define HMAX   64
#define LMAX   64
#define THRESH 30.0f
#define STG    49152          // stage: Ahi 8K | Alo 8K | Bhi 16K | Blo 16K

// ---------------- device scratch (allocation-free) ----------------
__device__ __align__(128) float          g_scores[(size_t)M_ * N_];
__device__ __align__(128) __nv_bfloat16  g_Xhi[(size_t)N_ * K_];
__device__ __align__(128) __nv_bfloat16  g_Xlo[(size_t)N_ * K_];
__device__ __align__(128) float          g_tmax[(size_t)NTILE * N_];
__device__ unsigned int g_gmax_u[N_];
__device__ int          g_cnt[N_];
__device__ int          g_hit_m[N_ * HMAX];
__device__ float        g_hit_s[N_ * HMAX];

// ---------------- helpers ----------------
__device__ __forceinline__ uint32_t s2u(const void* p) {
    return (uint32_t)__cvta_generic_to_shared(p);
}
// tile rows of 32 bf16 (64B); two logical rows per 128B phys row, XOR swizzle.
__device__ __forceinline__ uint32_t soff(uint32_t r, uint32_t c) {
    return (((r >> 1) << 3) + ((((r & 1) << 2) | c) ^ ((r >> 1) & 7))) << 4;
}
__device__ __forceinline__ void cp16(uint32_t dst, const void* src) {
    asm volatile("cp.async.cg.shared.global [%0], [%1], 16;" :: "r"(dst), "l"(src));
}
__device__ __forceinline__ void cp_commit() { asm volatile("cp.async.commit_group;"); }
__device__ __forceinline__ void cp_wait0() { asm volatile("cp.async.wait_group 0;" ::: "memory"); }

__device__ __forceinline__ void ldsm4(uint32_t* d, uint32_t addr) {
    asm volatile("ldmatrix.sync.aligned.m8n8.x4.shared.b16 {%0,%1,%2,%3}, [%4];"
        : "=r"(d[0]), "=r"(d[1]), "=r"(d[2]), "=r"(d[3]) : "r"(addr));
}
__device__ __forceinline__ void mma_bf16(float* c, const uint32_t* a, uint32_t b0, uint32_t b1) {
    asm volatile("mma.sync.aligned.m16n8k16.row.col.f32.bf16.bf16.f32 "
        "{%0,%1,%2,%3}, {%4,%5,%6,%7}, {%8,%9}, {%0,%1,%2,%3};"
        : "+f"(c[0]), "+f"(c[1]), "+f"(c[2]), "+f"(c[3])
        : "r"(a[0]), "r"(a[1]), "r"(a[2]), "r"(a[3]), "r"(b0), "r"(b1));
}
__device__ __forceinline__ unsigned int fkey(float f) {
    unsigned int b = __float_as_uint(f);
    return (b & 0x80000000u) ? ~b : (b | 0x80000000u);
}
__device__ __forceinline__ float funkey(unsigned int k) {
    unsigned int b = (k & 0x80000000u) ? (k & 0x7FFFFFFFu) : ~k;
    return __uint_as_float(b);
}
__device__ __forceinline__ uint32_t pk2(float x, float y) {   // bf16(x) low, bf16(y) high
    __nv_bfloat162 t = __floats2bfloat162_rn(x, y);
    return *(uint32_t*)&t;
}

// ---------------- zero per-launch state ----------------
__global__ void k_zero() {
    const int t = threadIdx.x;
    g_gmax_u[t] = 0u;
    g_cnt[t] = 0;
}

// ---------------- X fp32 -> (bf16 hi, lo), tiny ----------------
__global__ __launch_bounds__(256)
void k_split_x(const float* __restrict__ X) {
    size_t i = (size_t)blockIdx.x * 256 + threadIdx.x;
    if (i >= (size_t)N_ * K_ / 4) return;
    float4 v = ((const float4*)X)[i];
    float vv[4] = {v.x, v.y, v.z, v.w};
    unsigned long long ph = 0, pl = 0;
    #pragma unroll
    for (int c = 0; c < 4; c++) {
        __nv_bfloat16 h = __float2bfloat16(vv[c]);
        __nv_bfloat16 l = __float2bfloat16(vv[c] - __bfloat162float(h));
        ph |= (unsigned long long)(*(unsigned short*)&h) << (16 * c);
        pl |= (unsigned long long)(*(unsigned short*)&l) << (16 * c);
    }
    ((unsigned long long*)g_Xhi)[i] = ph;
    ((unsigned long long*)g_Xlo)[i] = pl;
}

// ---------------- GEMM1: scores[m][n] = 4 * D.X^T, 3-term split bf16 ----------
// CTA tile 128m x 256n, grid.y == 1 (D read exactly once, as fp32, split fused
// in-kernel). 8 warps = 2m x 4n, warp tile 64x64. Single __syncthreads per tile.
// Epilogue stores scores, per-(CTA,n) tile max, and global per-n max.
__global__ __launch_bounds__(256, 1)
void k_gemm1(const float* __restrict__ Dp) {
    extern __shared__ char smem[];
    const uint32_t sb = s2u(smem);
    const int tid = threadIdx.x, wid = tid >> 5, lane = tid & 31;
    const int m0 = blockIdx.x * 128;
    const int wm = (wid >> 2) * 64;        // 0 or 64
    const int wn = (wid & 3) * 64;         // 0,64,128,192

    int arow = m0 + (tid >> 1); if (arow >= M_) arow = M_ - 1;
    const float* aptr = Dp + (size_t)arow * K_ + (tid & 1) * 16;
    const uint32_t a_off  = soff(tid >> 1, (tid & 1) * 2);
    const uint32_t a_off2 = soff(tid >> 1, (tid & 1) * 2 + 1);

    float acc[4][8][4];
    #pragma unroll
    for (int a = 0; a < 4; a++)
        #pragma unroll
        for (int b = 0; b < 8; b++)
            #pragma unroll
            for (int q = 0; q < 4; q++) acc[a][b][q] = 0.f;

    float4 fA[4];
    auto ldgA = [&](int kt) {
        const float* p = aptr + kt * KT;
        fA[0] = *(const float4*)(p);
        fA[1] = *(const float4*)(p + 4);
        fA[2] = *(const float4*)(p + 8);
        fA[3] = *(const float4*)(p + 12);
    };
    auto stsA = [&](int s) {
        char* st = smem + s * STG;
        #pragma unroll
        for (int c2 = 0; c2 < 2; c2++) {
            float4 a = fA[2 * c2], b = fA[2 * c2 + 1];
            uint4 hi, lo;
            hi.x = pk2(a.x, a.y); hi.y = pk2(a.z, a.w);
            hi.z = pk2(b.x, b.y); hi.w = pk2(b.z, b.w);
            __nv_bfloat162 h0 = *(__nv_bfloat162*)&hi.x, h1 = *(__nv_bfloat162*)&hi.y;
            __nv_bfloat162 h2 = *(__nv_bfloat162*)&hi.z, h3 = *(__nv_bfloat162*)&hi.w;
            lo.x = pk2(a.x - __bfloat162float(h0.x), a.y - __bfloat162float(h0.y));
            lo.y = pk2(a.z - __bfloat162float(h1.x), a.w - __bfloat162float(h1.y));
            lo.z = pk2(b.x - __bfloat162float(h2.x), b.y - __bfloat162float(h2.y));
            lo.w = pk2(b.z - __bfloat162float(h3.x), b.w - __bfloat162float(h3.y));
            uint32_t off = c2 ? a_off2 : a_off;
            *(uint4*)(st + off)        = hi;
            *(uint4*)(st + 8192 + off) = lo;
        }
    };
    auto cpB = [&](int s, int kt) {
        const uint32_t st = sb + s * STG;
        const int k0 = kt * KT;
        #pragma unroll
        for (int q = 0; q < 4; q++) {
            int e = q * 256 + tid;
            int r = e >> 2, c = e & 3;
            uint32_t off = soff(r, c);
            size_t gb = (size_t)r * K_ + k0 + c * 8;
            cp16(st + 16384 + off, g_Xhi + gb);
            cp16(st + 32768 + off, g_Xlo + gb);
        }
        cp_commit();
    };

    ldgA(0);
    cpB(0, 0);
    stsA(0);

    for (int t = 0; t < NT1; t++) {
        cp_wait0();
        __syncthreads();
        const bool pf = (t + 1 < NT1);
        if (pf) { ldgA(t + 1); cpB((t + 1) & 1, t + 1); }

        const uint32_t st = sb + (t & 1) * STG;
        #pragma unroll
        for (int ks = 0; ks < 2; ks++) {
            const uint32_t cc = ks * 2 + (lane >> 4);
            uint32_t ah[4][4], al[4][4];
            #pragma unroll
            for (int mi = 0; mi < 4; mi++) {
                uint32_t a = st + soff(wm + mi * 16 + (lane & 15), cc);
                ldsm4(ah[mi], a);
                ldsm4(al[mi], a + 8192);
            }
            #pragma unroll
            for (int g = 0; g < 4; g++) {
                uint32_t bh[4], bl[4];
                uint32_t a = st + 16384 + soff(wn + g * 16 + (lane & 15), cc);
                ldsm4(bh, a);
                ldsm4(bl, a + 16384);
                #pragma unroll
                for (int mi = 0; mi < 4; mi++) {
                    mma_bf16(acc[mi][g*2],   ah[mi], bh[0], bh[2]);
                    mma_bf16(acc[mi][g*2+1], ah[mi], bh[1], bh[3]);
                    mma_bf16(acc[mi][g*2],   ah[mi], bl[0], bl[2]);
                    mma_bf16(acc[mi][g*2+1], ah[mi], bl[1], bl[3]);
                    mma_bf16(acc[mi][g*2],   al[mi], bh[0], bh[2]);
                    mma_bf16(acc[mi][g*2+1], al[mi], bh[1], bh[3]);
                }
            }
        }
        if (pf) stsA((t + 1) & 1);
    }

    // epilogue: scale, store scores, per-n warp maxima
    float mv0[8], mv1[8];
    #pragma unroll
    for (int mi = 0; mi < 4; mi++) {
        int m = m0 + wm + mi * 16 + (lane >> 2);
        #pragma unroll
        for (int nj = 0; nj < 8; nj++) {
            int n = wn + nj * 8 + (lane & 3) * 2;
            float v0 = acc[mi][nj][0] * INV_VAR, v1 = acc[mi][nj][1] * INV_VAR;
            float v2 = acc[mi][nj][2] * INV_VAR, v3 = acc[mi][nj][3] * INV_VAR;
            acc[mi][nj][0] = v0; acc[mi][nj][1] = v1;
            acc[mi][nj][2] = v2; acc[mi][nj][3] = v3;
            if (m < M_)     *(float2*)&g_scores[(size_t)m * N_ + n]       = make_float2(v0, v1);
            if (m + 8 < M_) *(float2*)&g_scores[(size_t)(m + 8) * N_ + n] = make_float2(v2, v3);
        }
    }
    #pragma unroll
    for (int nj = 0; nj < 8; nj++) {
        float v0 = -1e30f, v1 = -1e30f;
        #pragma unroll
        for (int mi = 0; mi < 4; mi++) {
            v0 = fmaxf(v0, fmaxf(acc[mi][nj][0], acc[mi][nj][2]));
            v1 = fmaxf(v1, fmaxf(acc[mi][nj][1], acc[mi][nj][3]));
        }
        #pragma unroll
        for (int mk = 4; mk < 32; mk <<= 1) {
            v0 = fmaxf(v0, __shfl_xor_sync(0xFFFFFFFFu, v0, mk));
            v1 = fmaxf(v1, __shfl_xor_sync(0xFFFFFFFFu, v1, mk));
        }
        mv0[nj] = v0; mv1[nj] = v1;
    }
    // combine the two m-warps per n (smem stage-0 region is dead here)
    float* s_max = (float*)smem;          // 256 floats
    __syncthreads();
    if (wm == 0 && (lane >> 2) == 0) {
        #pragma unroll
        for (int nj = 0; nj < 8; nj++) {
            int n = wn + nj * 8 + (lane & 3) * 2;
            s_max[n] = mv0[nj]; s_max[n + 1] = mv1[nj];
        }
    }
    __syncthreads();
    if (wm == 64 && (lane >> 2) == 0) {
        #pragma unroll
        for (int nj = 0; nj < 8; nj++) {
            int n = wn + nj * 8 + (lane & 3) * 2;
            float c0 = fmaxf(mv0[nj], s_max[n]);
            float c1 = fmaxf(mv1[nj], s_max[n + 1]);
            g_tmax[(size_t)blockIdx.x * N_ + n]     = c0;
            g_tmax[(size_t)blockIdx.x * N_ + n + 1] = c1;
            atomicMax(&g_gmax_u[n],     fkey(c0));
            atomicMax(&g_gmax_u[n + 1], fkey(c1));
        }
    }
}

// ---------------- select v3: all phases thread-parallel ----------------------
// Phase 1: 256 threads scan 391 tile maxima (<=2 loads/thread).
// Phase 2: rows of hot tiles flattened; every row is one load on its own thread.
__global__ __launch_bounds__(256)
void k_select() {
    __shared__ int s_list[LMAX];
    __shared__ int s_nlist, s_cnt;
    const int n = blockIdx.x, tid = threadIdx.x;
    if (tid == 0) { s_nlist = 0; s_cnt = 0; }
    __syncthreads();
    const float thr = funkey(g_gmax_u[n]) - THRESH;
    for (int b = tid; b < NTILE; b += 256) {
        if (g_tmax[(size_t)b * N_ + n] > thr) {
            int s = atomicAdd(&s_nlist, 1);
            if (s < LMAX) s_list[s] = b;
        }
    }
    __syncthreads();
    int nlist = s_nlist; if (nlist > LMAX) nlist = LMAX;
    const int nrows = nlist * 128;
    for (int r = tid; r < nrows; r += 256) {
        int m = s_list[r >> 7] * 128 + (r & 127);
        if (m < M_) {
            float v = g_scores[(size_t)m * N_ + n];
            if (v > thr) {
                int s = atomicAdd(&s_cnt, 1);
                if (s < HMAX) {
                    g_hit_m[n * HMAX + s] = m;
                    g_hit_s[n * HMAX + s] = v;
                }
            }
        }
    }
    __syncthreads();
    if (tid == 0) g_cnt[n] = s_cnt;
}

// ---------------- out[n][:] = sum_l w_l D[m_l][:] / sum_l w_l  (exact fp32) --
__global__ __launch_bounds__(256)
void k_out(const float* __restrict__ D, float* __restrict__ out) {
    __shared__ int   hm[HMAX];
    __shared__ float hs[HMAX];
    __shared__ float hw[HMAX];
    const int n = blockIdx.x, tid = threadIdx.x;
    int cnt = g_cnt[n]; if (cnt > HMAX) cnt = HMAX;
    if (tid < cnt) { hm[tid] = g_hit_m[n * HMAX + tid]; hs[tid] = g_hit_s[n * HMAX + tid]; }
    __syncthreads();
    if (tid == 0) {            // sort by m -> deterministic accumulation order
        for (int i = 1; i < cnt; i++) {
            int km = hm[i]; float ks_ = hs[i]; int j = i - 1;
            while (j >= 0 && hm[j] > km) { hm[j+1] = hm[j]; hs[j+1] = hs[j]; j--; }
            hm[j+1] = km; hs[j+1] = ks_;
        }
    }
    __syncthreads();
    const float gm = funkey(g_gmax_u[n]);
    if (tid < cnt) hw[tid] = expf(hs[tid] - gm);
    __syncthreads();
    float wsum = 0.f;
    for (int l = 0; l < cnt; l++) wsum += hw[l];
    const float inv = 1.0f / wsum;
    for (int j = tid; j < K_; j += 256) {
        float a = 0.f;
        for (int l = 0; l < cnt; l++)
            a += hw[l] * D[(size_t)hm[l] * K_ + j];
        out[(size_t)n * K_ + j] = a * inv;
    }
}

// ---------------- launch ----------------
extern "C" void kernel_launch(void* const* d_in, const int* in_sizes, int n_in,
                              void* d_out, int out_size) {
    (void)in_sizes; (void)n_in; (void)out_size;
    const float* X = (const float*)d_in[0];
    const float* D = (const float*)d_in[1];
    float* out = (float*)d_out;

    cudaFuncSetAttribute(k_gemm1, cudaFuncAttributeMaxDynamicSharedMemorySize, 2 * STG);

    k_zero<<<1, 256>>>();
    k_split_x<<<(N_ * K_ / 4 + 255) / 256, 256>>>(X);

    k_gemm1<<<(M_ + 127) / 128, 256, 2 * STG>>>(D);

    k_select<<<N_, 256>>>();
    k_out<<<N_, 256>>>(D, out);
}

// round 9
// speedup vs baseline: 1.2519x; 1.0546x over previous
#include <cuda_runtime.h>
#include <cuda_bf16.h>
#include <math.h>
#include <stdint.h>

#define N_     256
#define M_     50000
#define K_     3072
#define KT     32             // bf16 k per tile
#define NT1    (K_ / KT)      // 96
#define NTILE  391            // ceil(M/128)
#define INV_VAR 4.0f
#define HMAX   64
#define LMAX   64
#define THRESH 30.0f
#define STG    49152          // stage: Ahi 8K | Alo 8K | Bhi 16K | Blo 16K
#define NSTG   3

// ---------------- device scratch (allocation-free) ----------------
__device__ __align__(128) float          g_scores[(size_t)M_ * N_];
__device__ __align__(128) __nv_bfloat16  g_Xhi[(size_t)N_ * K_];
__device__ __align__(128) __nv_bfloat16  g_Xlo[(size_t)N_ * K_];
__device__ __align__(128) float          g_tmax[(size_t)NTILE * N_];
__device__ unsigned int g_gmax_u[N_];
__device__ int          g_cnt[N_];
__device__ int          g_hit_m[N_ * HMAX];
__device__ float        g_hit_s[N_ * HMAX];

// ---------------- helpers ----------------
__device__ __forceinline__ uint32_t s2u(const void* p) {
    return (uint32_t)__cvta_generic_to_shared(p);
}
// tile rows of 32 bf16 (64B); two logical rows per 128B phys row, XOR swizzle.
__device__ __forceinline__ uint32_t soff(uint32_t r, uint32_t c) {
    return (((r >> 1) << 3) + ((((r & 1) << 2) | c) ^ ((r >> 1) & 7))) << 4;
}
__device__ __forceinline__ void cp16(uint32_t dst, const void* src) {
    asm volatile("cp.async.cg.shared.global [%0], [%1], 16;" :: "r"(dst), "l"(src));
}
__device__ __forceinline__ void cp_commit() { asm volatile("cp.async.commit_group;"); }
__device__ __forceinline__ void cp_wait1() { asm volatile("cp.async.wait_group 1;" ::: "memory"); }
__device__ __forceinline__ void cp_wait0() { asm volatile("cp.async.wait_group 0;" ::: "memory"); }

__device__ __forceinline__ void ldsm4(uint32_t* d, uint32_t addr) {
    asm volatile("ldmatrix.sync.aligned.m8n8.x4.shared.b16 {%0,%1,%2,%3}, [%4];"
        : "=r"(d[0]), "=r"(d[1]), "=r"(d[2]), "=r"(d[3]) : "r"(addr));
}
__device__ __forceinline__ void mma_bf16(float* c, const uint32_t* a, uint32_t b0, uint32_t b1) {
    asm volatile("mma.sync.aligned.m16n8k16.row.col.f32.bf16.bf16.f32 "
        "{%0,%1,%2,%3}, {%4,%5,%6,%7}, {%8,%9}, {%0,%1,%2,%3};"
        : "+f"(c[0]), "+f"(c[1]), "+f"(c[2]), "+f"(c[3])
        : "r"(a[0]), "r"(a[1]), "r"(a[2]), "r"(a[3]), "r"(b0), "r"(b1));
}
__device__ __forceinline__ unsigned int fkey(float f) {
    unsigned int b = __float_as_uint(f);
    return (b & 0x80000000u) ? ~b : (b | 0x80000000u);
}
__device__ __forceinline__ float funkey(unsigned int k) {
    unsigned int b = (k & 0x80000000u) ? (k & 0x7FFFFFFFu) : ~k;
    return __uint_as_float(b);
}
__device__ __forceinline__ uint32_t pk2(float x, float y) {   // bf16(x) low, bf16(y) high
    __nv_bfloat162 t = __floats2bfloat162_rn(x, y);
    return *(uint32_t*)&t;
}

// ---------------- zero per-launch state ----------------
__global__ void k_zero() {
    const int t = threadIdx.x;
    g_gmax_u[t] = 0u;
    g_cnt[t] = 0;
}

// ---------------- X fp32 -> (bf16 hi, lo), tiny ----------------
__global__ __launch_bounds__(256)
void k_split_x(const float* __restrict__ X) {
    size_t i = (size_t)blockIdx.x * 256 + threadIdx.x;
    if (i >= (size_t)N_ * K_ / 4) return;
    float4 v = ((const float4*)X)[i];
    float vv[4] = {v.x, v.y, v.z, v.w};
    unsigned long long ph = 0, pl = 0;
    #pragma unroll
    for (int c = 0; c < 4; c++) {
        __nv_bfloat16 h = __float2bfloat16(vv[c]);
        __nv_bfloat16 l = __float2bfloat16(vv[c] - __bfloat162float(h));
        ph |= (unsigned long long)(*(unsigned short*)&h) << (16 * c);
        pl |= (unsigned long long)(*(unsigned short*)&l) << (16 * c);
    }
    ((unsigned long long*)g_Xhi)[i] = ph;
    ((unsigned long long*)g_Xlo)[i] = pl;
}

// ---------------- GEMM1: scores[m][n] = 4 * D.X^T, 3-term split bf16 ----------
// CTA tile 128m x 256n, grid.y == 1 (D read once as fp32, split fused).
// 8 warps = 2m x 4n, warp tile 64x64. 3-stage cp.async ring, prefetch dist 2.
__global__ __launch_bounds__(256, 1)
void k_gemm1(const float* __restrict__ Dp) {
    extern __shared__ char smem[];
    const uint32_t sb = s2u(smem);
    const int tid = threadIdx.x, wid = tid >> 5, lane = tid & 31;
    const int m0 = blockIdx.x * 128;
    const int wm = (wid >> 2) * 64;        // 0 or 64
    const int wn = (wid & 3) * 64;         // 0,64,128,192

    int arow = m0 + (tid >> 1); if (arow >= M_) arow = M_ - 1;
    const float* aptr = Dp + (size_t)arow * K_ + (tid & 1) * 16;
    const uint32_t a_off  = soff(tid >> 1, (tid & 1) * 2);
    const uint32_t a_off2 = soff(tid >> 1, (tid & 1) * 2 + 1);

    float acc[4][8][4];
    #pragma unroll
    for (int a = 0; a < 4; a++)
        #pragma unroll
        for (int b = 0; b < 8; b++)
            #pragma unroll
            for (int q = 0; q < 4; q++) acc[a][b][q] = 0.f;

    float4 fA[4];
    auto ldgA = [&](int kt) {
        const float* p = aptr + kt * KT;
        fA[0] = *(const float4*)(p);
        fA[1] = *(const float4*)(p + 4);
        fA[2] = *(const float4*)(p + 8);
        fA[3] = *(const float4*)(p + 12);
    };
    auto stsA = [&](int s) {
        char* st = smem + s * STG;
        #pragma unroll
        for (int c2 = 0; c2 < 2; c2++) {
            float4 a = fA[2 * c2], b = fA[2 * c2 + 1];
            uint4 hi, lo;
            hi.x = pk2(a.x, a.y); hi.y = pk2(a.z, a.w);
            hi.z = pk2(b.x, b.y); hi.w = pk2(b.z, b.w);
            __nv_bfloat162 h0 = *(__nv_bfloat162*)&hi.x, h1 = *(__nv_bfloat162*)&hi.y;
            __nv_bfloat162 h2 = *(__nv_bfloat162*)&hi.z, h3 = *(__nv_bfloat162*)&hi.w;
            lo.x = pk2(a.x - __bfloat162float(h0.x), a.y - __bfloat162float(h0.y));
            lo.y = pk2(a.z - __bfloat162float(h1.x), a.w - __bfloat162float(h1.y));
            lo.z = pk2(b.x - __bfloat162float(h2.x), b.y - __bfloat162float(h2.y));
            lo.w = pk2(b.z - __bfloat162float(h3.x), b.w - __bfloat162float(h3.y));
            uint32_t off = c2 ? a_off2 : a_off;
            *(uint4*)(st + off)        = hi;
            *(uint4*)(st + 8192 + off) = lo;
        }
    };
    auto cpB = [&](int s, int kt) {
        const uint32_t st = sb + s * STG;
        const int k0 = kt * KT;
        #pragma unroll
        for (int q = 0; q < 4; q++) {
            int e = q * 256 + tid;
            int r = e >> 2, c = e & 3;
            uint32_t off = soff(r, c);
            size_t gb = (size_t)r * K_ + k0 + c * 8;
            cp16(st + 16384 + off, g_Xhi + gb);
            cp16(st + 32768 + off, g_Xlo + gb);
        }
        cp_commit();
    };

    // prologue: stages 0 and 1
    ldgA(0); cpB(0, 0); stsA(0);
    ldgA(1); cpB(1, 1); stsA(1);

    for (int t = 0; t < NT1; t++) {
        const int pf = (t + 2 < NT1);
        if (pf) ldgA(t + 2);            // pure LDG, no smem hazard
        if (pf) cp_wait1(); else cp_wait0();
        __syncthreads();
        const int sNew = (t + 2) % NSTG;
        if (pf) cpB(sNew, t + 2);

        const uint32_t st = sb + (t % NSTG) * STG;
        #pragma unroll
        for (int ks = 0; ks < 2; ks++) {
            const uint32_t cc = ks * 2 + (lane >> 4);
            uint32_t ah[4][4], al[4][4];
            #pragma unroll
            for (int mi = 0; mi < 4; mi++) {
                uint32_t a = st + soff(wm + mi * 16 + (lane & 15), cc);
                ldsm4(ah[mi], a);
                ldsm4(al[mi], a + 8192);
            }
            #pragma unroll
            for (int g = 0; g < 4; g++) {
                uint32_t bh[4], bl[4];
                uint32_t a = st + 16384 + soff(wn + g * 16 + (lane & 15), cc);
                ldsm4(bh, a);
                ldsm4(bl, a + 16384);
                #pragma unroll
                for (int mi = 0; mi < 4; mi++) {
                    mma_bf16(acc[mi][g*2],   ah[mi], bh[0], bh[2]);
                    mma_bf16(acc[mi][g*2+1], ah[mi], bh[1], bh[3]);
                    mma_bf16(acc[mi][g*2],   ah[mi], bl[0], bl[2]);
                    mma_bf16(acc[mi][g*2+1], ah[mi], bl[1], bl[3]);
                    mma_bf16(acc[mi][g*2],   al[mi], bh[0], bh[2]);
                    mma_bf16(acc[mi][g*2+1], al[mi], bh[1], bh[3]);
                }
            }
        }
        if (pf) stsA(sNew);
    }

    // epilogue: scale, store scores, per-n warp maxima
    float mv0[8], mv1[8];
    #pragma unroll
    for (int mi = 0; mi < 4; mi++) {
        int m = m0 + wm + mi * 16 + (lane >> 2);
        #pragma unroll
        for (int nj = 0; nj < 8; nj++) {
            int n = wn + nj * 8 + (lane & 3) * 2;
            float v0 = acc[mi][nj][0] * INV_VAR, v1 = acc[mi][nj][1] * INV_VAR;
            float v2 = acc[mi][nj][2] * INV_VAR, v3 = acc[mi][nj][3] * INV_VAR;
            acc[mi][nj][0] = v0; acc[mi][nj][1] = v1;
            acc[mi][nj][2] = v2; acc[mi][nj][3] = v3;
            if (m < M_)     *(float2*)&g_scores[(size_t)m * N_ + n]       = make_float2(v0, v1);
            if (m + 8 < M_) *(float2*)&g_scores[(size_t)(m + 8) * N_ + n] = make_float2(v2, v3);
        }
    }
    #pragma unroll
    for (int nj = 0; nj < 8; nj++) {
        float v0 = -1e30f, v1 = -1e30f;
        #pragma unroll
        for (int mi = 0; mi < 4; mi++) {
            v0 = fmaxf(v0, fmaxf(acc[mi][nj][0], acc[mi][nj][2]));
            v1 = fmaxf(v1, fmaxf(acc[mi][nj][1], acc[mi][nj][3]));
        }
        #pragma unroll
        for (int mk = 4; mk < 32; mk <<= 1) {
            v0 = fmaxf(v0, __shfl_xor_sync(0xFFFFFFFFu, v0, mk));
            v1 = fmaxf(v1, __shfl_xor_sync(0xFFFFFFFFu, v1, mk));
        }
        mv0[nj] = v0; mv1[nj] = v1;
    }
    float* s_max = (float*)smem;          // stage-0 region dead after final barrier
    __syncthreads();
    if (wm == 0 && (lane >> 2) == 0) {
        #pragma unroll
        for (int nj = 0; nj < 8; nj++) {
            int n = wn + nj * 8 + (lane & 3) * 2;
            s_max[n] = mv0[nj]; s_max[n + 1] = mv1[nj];
        }
    }
    __syncthreads();
    if (wm == 64 && (lane >> 2) == 0) {
        #pragma unroll
        for (int nj = 0; nj < 8; nj++) {
            int n = wn + nj * 8 + (lane & 3) * 2;
            float c0 = fmaxf(mv0[nj], s_max[n]);
            float c1 = fmaxf(mv1[nj], s_max[n + 1]);
            g_tmax[(size_t)blockIdx.x * N_ + n]     = c0;
            g_tmax[(size_t)blockIdx.x * N_ + n + 1] = c1;
            atomicMax(&g_gmax_u[n],     fkey(c0));
            atomicMax(&g_gmax_u[n + 1], fkey(c1));
        }
    }
}

// ---------------- select: all phases thread-parallel -------------------------
__global__ __launch_bounds__(256)
void k_select() {
    __shared__ int s_list[LMAX];
    __shared__ int s_nlist, s_cnt;
    const int n = blockIdx.x, tid = threadIdx.x;
    if (tid == 0) { s_nlist = 0; s_cnt = 0; }
    __syncthreads();
    const float thr = funkey(g_gmax_u[n]) - THRESH;
    for (int b = tid; b < NTILE; b += 256) {
        if (g_tmax[(size_t)b * N_ + n] > thr) {
            int s = atomicAdd(&s_nlist, 1);
            if (s < LMAX) s_list[s] = b;
        }
    }
    __syncthreads();
    int nlist = s_nlist; if (nlist > LMAX) nlist = LMAX;
    const int nrows = nlist * 128;
    for (int r = tid; r < nrows; r += 256) {
        int m = s_list[r >> 7] * 128 + (r & 127);
        if (m < M_) {
            float v = g_scores[(size_t)m * N_ + n];
            if (v > thr) {
                int s = atomicAdd(&s_cnt, 1);
                if (s < HMAX) {
                    g_hit_m[n * HMAX + s] = m;
                    g_hit_s[n * HMAX + s] = v;
                }
            }
        }
    }
    __syncthreads();
    if (tid == 0) g_cnt[n] = s_cnt;
}

// ---------------- out[n][:] = sum_l w_l D[m_l][:] / sum_l w_l  (exact fp32) --
__global__ __launch_bounds__(256)
void k_out(const float* __restrict__ D, float* __restrict__ out) {
    __shared__ int   hm[HMAX];
    __shared__ float hs[HMAX];
    __shared__ float hw[HMAX];
    const int n = blockIdx.x, tid = threadIdx.x;
    int cnt = g_cnt[n]; if (cnt > HMAX) cnt = HMAX;
    if (tid < cnt) { hm[tid] = g_hit_m[n * HMAX + tid]; hs[tid] = g_hit_s[n * HMAX + tid]; }
    __syncthreads();
    if (tid == 0) {            // sort by m -> deterministic accumulation order
        for (int i = 1; i < cnt; i++) {
            int km = hm[i]; float ks_ = hs[i]; int j = i - 1;
            while (j >= 0 && hm[j] > km) { hm[j+1] = hm[j]; hs[j+1] = hs[j]; j--; }
            hm[j+1] = km; hs[j+1] = ks_;
        }
    }
    __syncthreads();
    const float gm = funkey(g_gmax_u[n]);
    if (tid < cnt) hw[tid] = expf(hs[tid] - gm);
    __syncthreads();
    float wsum = 0.f;
    for (int l = 0; l < cnt; l++) wsum += hw[l];
    const float inv = 1.0f / wsum;
    for (int j = tid; j < K_; j += 256) {
        float a = 0.f;
        for (int l = 0; l < cnt; l++)
            a += hw[l] * D[(size_t)hm[l] * K_ + j];
        out[(size_t)n * K_ + j] = a * inv;
    }
}

// ---------------- launch ----------------
extern "C" void kernel_launch(void* const* d_in, const int* in_sizes, int n_in,
                              void* d_out, int out_size) {
    (void)in_sizes; (void)n_in; (void)out_size;
    const float* X = (const float*)d_in[0];
    const float* D = (const float*)d_in[1];
    float* out = (float*)d_out;

    cudaFuncSetAttribute(k_gemm1, cudaFuncAttributeMaxDynamicSharedMemorySize, NSTG * STG);

    k_zero<<<1, 256>>>();
    k_split_x<<<(N_ * K_ / 4 + 255) / 256, 256>>>(X);

    k_gemm1<<<(M_ + 127) / 128, 256, NSTG * STG>>>(D);

    k_select<<<N_, 256>>>();
    k_out<<<N_, 256>>>(D, out);
}

// round 10
// speedup vs baseline: 2.6996x; 2.1563x over previous
#include <cuda_runtime.h>
#include <cuda_bf16.h>
#include <math.h>
#include <stdint.h>

#define N_     256
#define M_     50000
#define K_     3072
#define KT     32             // bf16 k per tile
#define NT1    (K_ / KT)      // 96
#define NTILE  391            // ceil(M/128)
#define INV_VAR 4.0f
#define HMAX   64
#define LMAX   64
#define THRESH 36.0f          // 30 (softmax support) + 6 (hi-only bf16 score error margin)
#define STG    24576          // stage: Ahi 8K | Bhi 16K
#define NSTG   3

// ---------------- device scratch (allocation-free) ----------------
__device__ __align__(128) float          g_scores[(size_t)M_ * N_];
__device__ __align__(128) __nv_bfloat16  g_Xhi[(size_t)N_ * K_];
__device__ __align__(128) float          g_tmax[(size_t)NTILE * N_];
__device__ unsigned int g_gmax_u[N_];
__device__ int          g_cnt[N_];
__device__ int          g_hit_m[N_ * HMAX];

// ---------------- helpers ----------------
__device__ __forceinline__ uint32_t s2u(const void* p) {
    return (uint32_t)__cvta_generic_to_shared(p);
}
// tile rows of 32 bf16 (64B); two logical rows per 128B phys row, XOR swizzle.
__device__ __forceinline__ uint32_t soff(uint32_t r, uint32_t c) {
    return (((r >> 1) << 3) + ((((r & 1) << 2) | c) ^ ((r >> 1) & 7))) << 4;
}
__device__ __forceinline__ void cp16(uint32_t dst, const void* src) {
    asm volatile("cp.async.cg.shared.global [%0], [%1], 16;" :: "r"(dst), "l"(src));
}
__device__ __forceinline__ void cp_commit() { asm volatile("cp.async.commit_group;"); }
__device__ __forceinline__ void cp_wait1() { asm volatile("cp.async.wait_group 1;" ::: "memory"); }
__device__ __forceinline__ void cp_wait0() { asm volatile("cp.async.wait_group 0;" ::: "memory"); }

__device__ __forceinline__ void ldsm4(uint32_t* d, uint32_t addr) {
    asm volatile("ldmatrix.sync.aligned.m8n8.x4.shared.b16 {%0,%1,%2,%3}, [%4];"
        : "=r"(d[0]), "=r"(d[1]), "=r"(d[2]), "=r"(d[3]) : "r"(addr));
}
__device__ __forceinline__ void mma_bf16(float* c, const uint32_t* a, uint32_t b0, uint32_t b1) {
    asm volatile("mma.sync.aligned.m16n8k16.row.col.f32.bf16.bf16.f32 "
        "{%0,%1,%2,%3}, {%4,%5,%6,%7}, {%8,%9}, {%0,%1,%2,%3};"
        : "+f"(c[0]), "+f"(c[1]), "+f"(c[2]), "+f"(c[3])
        : "r"(a[0]), "r"(a[1]), "r"(a[2]), "r"(a[3]), "r"(b0), "r"(b1));
}
__device__ __forceinline__ unsigned int fkey(float f) {
    unsigned int b = __float_as_uint(f);
    return (b & 0x80000000u) ? ~b : (b | 0x80000000u);
}
__device__ __forceinline__ float funkey(unsigned int k) {
    unsigned int b = (k & 0x80000000u) ? (k & 0x7FFFFFFFu) : ~k;
    return __uint_as_float(b);
}
__device__ __forceinline__ uint32_t pk2(float x, float y) {   // bf16(x) low, bf16(y) high
    __nv_bfloat162 t = __floats2bfloat162_rn(x, y);
    return *(uint32_t*)&t;
}

// ---------------- zero per-launch state ----------------
__global__ void k_zero() {
    const int t = threadIdx.x;
    g_gmax_u[t] = 0u;
    g_cnt[t] = 0;
}

// ---------------- X fp32 -> bf16 hi, tiny ----------------
__global__ __launch_bounds__(256)
void k_split_x(const float* __restrict__ X) {
    size_t i = (size_t)blockIdx.x * 256 + threadIdx.x;
    if (i >= (size_t)N_ * K_ / 4) return;
    float4 v = ((const float4*)X)[i];
    unsigned long long ph = (unsigned long long)pk2(v.x, v.y)
                          | ((unsigned long long)pk2(v.z, v.w) << 32);
    ((unsigned long long*)g_Xhi)[i] = ph;
}

// ---------------- GEMM1: approx scores[m][n] = 4 * bf16(D).bf16(X)^T ---------
// CTA tile 128m x 256n, grid.y == 1 (D read once as fp32, converted in-kernel).
// 8 warps = 2m x 4n, warp tile 64x64. 3-stage cp.async ring, prefetch dist 2.
__global__ __launch_bounds__(256, 1)
void k_gemm1(const float* __restrict__ Dp) {
    extern __shared__ char smem[];
    const uint32_t sb = s2u(smem);
    const int tid = threadIdx.x, wid = tid >> 5, lane = tid & 31;
    const int m0 = blockIdx.x * 128;
    const int wm = (wid >> 2) * 64;        // 0 or 64
    const int wn = (wid & 3) * 64;         // 0,64,128,192

    int arow = m0 + (tid >> 1); if (arow >= M_) arow = M_ - 1;
    const float* aptr = Dp + (size_t)arow * K_ + (tid & 1) * 16;
    const uint32_t a_off  = soff(tid >> 1, (tid & 1) * 2);
    const uint32_t a_off2 = soff(tid >> 1, (tid & 1) * 2 + 1);

    float acc[4][8][4];
    #pragma unroll
    for (int a = 0; a < 4; a++)
        #pragma unroll
        for (int b = 0; b < 8; b++)
            #pragma unroll
            for (int q = 0; q < 4; q++) acc[a][b][q] = 0.f;

    float4 fA[4];
    auto ldgA = [&](int kt) {
        const float* p = aptr + kt * KT;
        fA[0] = *(const float4*)(p);
        fA[1] = *(const float4*)(p + 4);
        fA[2] = *(const float4*)(p + 8);
        fA[3] = *(const float4*)(p + 12);
    };
    auto stsA = [&](int s) {
        char* st = smem + s * STG;
        #pragma unroll
        for (int c2 = 0; c2 < 2; c2++) {
            float4 a = fA[2 * c2], b = fA[2 * c2 + 1];
            uint4 hi;
            hi.x = pk2(a.x, a.y); hi.y = pk2(a.z, a.w);
            hi.z = pk2(b.x, b.y); hi.w = pk2(b.z, b.w);
            *(uint4*)(st + (c2 ? a_off2 : a_off)) = hi;
        }
    };
    auto cpB = [&](int s, int kt) {
        const uint32_t st = sb + s * STG;
        const int k0 = kt * KT;
        #pragma unroll
        for (int q = 0; q < 4; q++) {
            int e = q * 256 + tid;
            int r = e >> 2, c = e & 3;
            cp16(st + 8192 + soff(r, c), g_Xhi + (size_t)r * K_ + k0 + c * 8);
        }
        cp_commit();
    };

    // prologue: stages 0 and 1
    ldgA(0); cpB(0, 0); stsA(0);
    ldgA(1); cpB(1, 1); stsA(1);

    for (int t = 0; t < NT1; t++) {
        const int pf = (t + 2 < NT1);
        if (pf) ldgA(t + 2);            // pure LDG, no smem hazard
        if (pf) cp_wait1(); else cp_wait0();
        __syncthreads();
        const int sNew = (t + 2) % NSTG;
        if (pf) cpB(sNew, t + 2);

        const uint32_t st = sb + (t % NSTG) * STG;
        #pragma unroll
        for (int ks = 0; ks < 2; ks++) {
            const uint32_t cc = ks * 2 + (lane >> 4);
            uint32_t ah[4][4];
            #pragma unroll
            for (int mi = 0; mi < 4; mi++)
                ldsm4(ah[mi], st + soff(wm + mi * 16 + (lane & 15), cc));
            #pragma unroll
            for (int g = 0; g < 4; g++) {
                uint32_t bh[4];
                ldsm4(bh, st + 8192 + soff(wn + g * 16 + (lane & 15), cc));
                #pragma unroll
                for (int mi = 0; mi < 4; mi++) {
                    mma_bf16(acc[mi][g*2],   ah[mi], bh[0], bh[2]);
                    mma_bf16(acc[mi][g*2+1], ah[mi], bh[1], bh[3]);
                }
            }
        }
        if (pf) stsA(sNew);
    }

    // epilogue: scale, store scores, per-n warp maxima
    float mv0[8], mv1[8];
    #pragma unroll
    for (int mi = 0; mi < 4; mi++) {
        int m = m0 + wm + mi * 16 + (lane >> 2);
        #pragma unroll
        for (int nj = 0; nj < 8; nj++) {
            int n = wn + nj * 8 + (lane & 3) * 2;
            float v0 = acc[mi][nj][0] * INV_VAR, v1 = acc[mi][nj][1] * INV_VAR;
            float v2 = acc[mi][nj][2] * INV_VAR, v3 = acc[mi][nj][3] * INV_VAR;
            acc[mi][nj][0] = v0; acc[mi][nj][1] = v1;
            acc[mi][nj][2] = v2; acc[mi][nj][3] = v3;
            if (m < M_)     *(float2*)&g_scores[(size_t)m * N_ + n]       = make_float2(v0, v1);
            if (m + 8 < M_) *(float2*)&g_scores[(size_t)(m + 8) * N_ + n] = make_float2(v2, v3);
        }
    }
    #pragma unroll
    for (int nj = 0; nj < 8; nj++) {
        float v0 = -1e30f, v1 = -1e30f;
        #pragma unroll
        for (int mi = 0; mi < 4; mi++) {
            v0 = fmaxf(v0, fmaxf(acc[mi][nj][0], acc[mi][nj][2]));
            v1 = fmaxf(v1, fmaxf(acc[mi][nj][1], acc[mi][nj][3]));
        }
        #pragma unroll
        for (int mk = 4; mk < 32; mk <<= 1) {
            v0 = fmaxf(v0, __shfl_xor_sync(0xFFFFFFFFu, v0, mk));
            v1 = fmaxf(v1, __shfl_xor_sync(0xFFFFFFFFu, v1, mk));
        }
        mv0[nj] = v0; mv1[nj] = v1;
    }
    float* s_max = (float*)smem;          // stage-0 region dead after final barrier
    __syncthreads();
    if (wm == 0 && (lane >> 2) == 0) {
        #pragma unroll
        for (int nj = 0; nj < 8; nj++) {
            int n = wn + nj * 8 + (lane & 3) * 2;
            s_max[n] = mv0[nj]; s_max[n + 1] = mv1[nj];
        }
    }
    __syncthreads();
    if (wm == 64 && (lane >> 2) == 0) {
        #pragma unroll
        for (int nj = 0; nj < 8; nj++) {
            int n = wn + nj * 8 + (lane & 3) * 2;
            float c0 = fmaxf(mv0[nj], s_max[n]);
            float c1 = fmaxf(mv1[nj], s_max[n + 1]);
            g_tmax[(size_t)blockIdx.x * N_ + n]     = c0;
            g_tmax[(size_t)blockIdx.x * N_ + n + 1] = c1;
            atomicMax(&g_gmax_u[n],     fkey(c0));
            atomicMax(&g_gmax_u[n + 1], fkey(c1));
        }
    }
}

// ---------------- select (approx scores, widened margin) ---------------------
__global__ __launch_bounds__(256)
void k_select() {
    __shared__ int s_list[LMAX];
    __shared__ int s_nlist, s_cnt;
    const int n = blockIdx.x, tid = threadIdx.x;
    if (tid == 0) { s_nlist = 0; s_cnt = 0; }
    __syncthreads();
    const float thr = funkey(g_gmax_u[n]) - THRESH;
    for (int b = tid; b < NTILE; b += 256) {
        if (g_tmax[(size_t)b * N_ + n] > thr) {
            int s = atomicAdd(&s_nlist, 1);
            if (s < LMAX) s_list[s] = b;
        }
    }
    __syncthreads();
    int nlist = s_nlist; if (nlist > LMAX) nlist = LMAX;
    const int nrows = nlist * 128;
    for (int r = tid; r < nrows; r += 256) {
        int m = s_list[r >> 7] * 128 + (r & 127);
        if (m < M_) {
            if (g_scores[(size_t)m * N_ + n] > thr) {
                int s = atomicAdd(&s_cnt, 1);
                if (s < HMAX) g_hit_m[n * HMAX + s] = m;
            }
        }
    }
    __syncthreads();
    if (tid == 0) g_cnt[n] = s_cnt;
}

// ---------------- out: exact fp32 scores for candidates, exact softmax -------
__global__ __launch_bounds__(256)
void k_out(const float* __restrict__ X, const float* __restrict__ D,
           float* __restrict__ out) {
    __shared__ int   hm[HMAX];
    __shared__ float s_sc[HMAX];
    __shared__ float hw[HMAX];
    __shared__ float red[256];
    const int n = blockIdx.x, tid = threadIdx.x;
    int cnt = g_cnt[n]; if (cnt > HMAX) cnt = HMAX;
    if (tid < cnt) hm[tid] = g_hit_m[n * HMAX + tid];
    __syncthreads();
    if (tid == 0) {            // sort by m -> deterministic everything below
        for (int i = 1; i < cnt; i++) {
            int km = hm[i]; int j = i - 1;
            while (j >= 0 && hm[j] > km) { hm[j+1] = hm[j]; j--; }
            hm[j+1] = km;
        }
    }
    __syncthreads();

    // x row in registers (12 floats per thread)
    float xr[12];
    #pragma unroll
    for (int q = 0; q < 12; q++) xr[q] = X[(size_t)n * K_ + tid + q * 256];

    // exact fp32 scores via fixed-tree block reduction (deterministic)
    for (int l = 0; l < cnt; l++) {
        const float* dr = D + (size_t)hm[l] * K_;
        float p = 0.f;
        #pragma unroll
        for (int q = 0; q < 12; q++) p += xr[q] * dr[tid + q * 256];
        red[tid] = p; __syncthreads();
        #pragma unroll
        for (int off = 128; off > 0; off >>= 1) {
            if (tid < off) red[tid] += red[tid + off];
            __syncthreads();
        }
        if (tid == 0) s_sc[l] = red[0] * INV_VAR;
        __syncthreads();
    }

    float gm = -1e30f;
    for (int l = 0; l < cnt; l++) gm = fmaxf(gm, s_sc[l]);
    if (tid < cnt) hw[tid] = expf(s_sc[tid] - gm);
    __syncthreads();
    float wsum = 0.f;
    for (int l = 0; l < cnt; l++) wsum += hw[l];
    const float inv = 1.0f / wsum;

    #pragma unroll
    for (int q = 0; q < 12; q++) {
        int j = tid + q * 256;
        float a = 0.f;
        for (int l = 0; l < cnt; l++)
            a += hw[l] * D[(size_t)hm[l] * K_ + j];
        out[(size_t)n * K_ + j] = a * inv;
    }
}

// ---------------- launch ----------------
extern "C" void kernel_launch(void* const* d_in, const int* in_sizes, int n_in,
                              void* d_out, int out_size) {
    (void)in_sizes; (void)n_in; (void)out_size;
    const float* X = (const float*)d_in[0];
    const float* D = (const float*)d_in[1];
    float* out = (float*)d_out;

    cudaFuncSetAttribute(k_gemm1, cudaFuncAttributeMaxDynamicSharedMemorySize, NSTG * STG);

    k_zero<<<1, 256>>>();
    k_split_x<<<(N_ * K_ / 4 + 255) / 256, 256>>>(X);

    k_gemm1<<<(M_ + 127) / 128, 256, NSTG * STG>>>(D);

    k_select<<<N_, 256>>>();
    k_out<<<N_, 256>>>(X, D, out);
}

// round 11
// speedup vs baseline: 3.0641x; 1.1350x over previous
#include <cuda_runtime.h>
#include <cuda_bf16.h>
#include <math.h>
#include <stdint.h>

#define N_     256
#define M_     50000
#define K_     3072
#define KT     64             // bf16 k per tile (128B rows, classic SW128)
#define NT1    (K_ / KT)      // 48
#define NTILE  391            // ceil(M/128)
#define INV_VAR 4.0f
#define HMAX   64
#define LMAX   64
#define THRESH 38.0f          // 30 (softmax support) + 8 (bf16 score + bf16 store margin)
#define STG    49152          // stage: A 16K | B 32K
#define NSTG   3

// ---------------- device scratch (allocation-free) ----------------
__device__ __align__(128) __nv_bfloat16  g_scores[(size_t)M_ * N_];
__device__ __align__(128) __nv_bfloat16  g_Xhi[(size_t)N_ * K_];
__device__ __align__(128) float          g_tmax[(size_t)NTILE * N_];
__device__ unsigned int g_gmax_u[N_];
__device__ int          g_cnt[N_];
__device__ int          g_hit_m[N_ * HMAX];

// ---------------- helpers ----------------
__device__ __forceinline__ uint32_t s2u(const void* p) {
    return (uint32_t)__cvta_generic_to_shared(p);
}
// 128B rows, classic SW128: chunk c (16B) XOR row&7
__device__ __forceinline__ uint32_t soff64(uint32_t r, uint32_t c) {
    return (r << 7) + ((c ^ (r & 7)) << 4);
}
__device__ __forceinline__ void cp16(uint32_t dst, const void* src) {
    asm volatile("cp.async.cg.shared.global [%0], [%1], 16;" :: "r"(dst), "l"(src));
}
__device__ __forceinline__ void cp_commit() { asm volatile("cp.async.commit_group;"); }
__device__ __forceinline__ void cp_wait1() { asm volatile("cp.async.wait_group 1;" ::: "memory"); }
__device__ __forceinline__ void cp_wait0() { asm volatile("cp.async.wait_group 0;" ::: "memory"); }

__device__ __forceinline__ void ldsm4(uint32_t* d, uint32_t addr) {
    asm volatile("ldmatrix.sync.aligned.m8n8.x4.shared.b16 {%0,%1,%2,%3}, [%4];"
        : "=r"(d[0]), "=r"(d[1]), "=r"(d[2]), "=r"(d[3]) : "r"(addr));
}
__device__ __forceinline__ void mma_bf16(float* c, const uint32_t* a, uint32_t b0, uint32_t b1) {
    asm volatile("mma.sync.aligned.m16n8k16.row.col.f32.bf16.bf16.f32 "
        "{%0,%1,%2,%3}, {%4,%5,%6,%7}, {%8,%9}, {%0,%1,%2,%3};"
        : "+f"(c[0]), "+f"(c[1]), "+f"(c[2]), "+f"(c[3])
        : "r"(a[0]), "r"(a[1]), "r"(a[2]), "r"(a[3]), "r"(b0), "r"(b1));
}
__device__ __forceinline__ unsigned int fkey(float f) {
    unsigned int b = __float_as_uint(f);
    return (b & 0x80000000u) ? ~b : (b | 0x80000000u);
}
__device__ __forceinline__ float funkey(unsigned int k) {
    unsigned int b = (k & 0x80000000u) ? (k & 0x7FFFFFFFu) : ~k;
    return __uint_as_float(b);
}
__device__ __forceinline__ uint32_t pk2(float x, float y) {   // bf16(x) low, bf16(y) high
    __nv_bfloat162 t = __floats2bfloat162_rn(x, y);
    return *(uint32_t*)&t;
}

// ---------------- X fp32 -> bf16 (+ zero per-launch state in block 0) --------
__global__ __launch_bounds__(256)
void k_split_x(const float* __restrict__ X) {
    if (blockIdx.x == 0) {
        g_gmax_u[threadIdx.x] = 0u;
        g_cnt[threadIdx.x] = 0;
    }
    size_t i = (size_t)blockIdx.x * 256 + threadIdx.x;
    if (i >= (size_t)N_ * K_ / 4) return;
    float4 v = ((const float4*)X)[i];
    unsigned long long ph = (unsigned long long)pk2(v.x, v.y)
                          | ((unsigned long long)pk2(v.z, v.w) << 32);
    ((unsigned long long*)g_Xhi)[i] = ph;
}

// ---------------- GEMM1: approx scores[m][n] = 4 * bf16(D).bf16(X)^T ---------
// CTA tile 128m x 256n. 8 warps = 2m x 4n, warp tile 64x64. KT=64, 3-stage
// ring, prefetch distance 2. D read once (fp32), converted in-register.
__global__ __launch_bounds__(256, 1)
void k_gemm1(const float* __restrict__ Dp) {
    extern __shared__ char smem[];
    const uint32_t sb = s2u(smem);
    const int tid = threadIdx.x, wid = tid >> 5, lane = tid & 31;
    const int m0 = blockIdx.x * 128;
    const int wm = (wid >> 2) * 64;        // 0 or 64
    const int wn = (wid & 3) * 64;         // 0,64,128,192

    // A loader geometry: element e = tid + p*256; row = e>>2 (0..127), quarter q = e&3
    const float* aPtr[2];
    uint32_t aOff[2][2];
    #pragma unroll
    for (int p = 0; p < 2; p++) {
        int e = tid + p * 256;
        int row = e >> 2, q = e & 3;
        int m = m0 + row; if (m >= M_) m = M_ - 1;
        aPtr[p] = Dp + (size_t)m * K_ + q * 16;
        aOff[p][0] = soff64(row, q * 2);
        aOff[p][1] = soff64(row, q * 2 + 1);
    }

    float acc[4][8][4];
    #pragma unroll
    for (int a = 0; a < 4; a++)
        #pragma unroll
        for (int b = 0; b < 8; b++)
            #pragma unroll
            for (int q = 0; q < 4; q++) acc[a][b][q] = 0.f;

    float4 fA[8];
    auto ldgA = [&](int kt) {
        #pragma unroll
        for (int p = 0; p < 2; p++) {
            const float* ptr = aPtr[p] + kt * KT;
            fA[p*4+0] = *(const float4*)(ptr);
            fA[p*4+1] = *(const float4*)(ptr + 4);
            fA[p*4+2] = *(const float4*)(ptr + 8);
            fA[p*4+3] = *(const float4*)(ptr + 12);
        }
    };
    auto stsA = [&](int s) {
        char* st = smem + s * STG;
        #pragma unroll
        for (int p = 0; p < 2; p++) {
            float4 a = fA[p*4+0], b = fA[p*4+1], c = fA[p*4+2], d = fA[p*4+3];
            uint4 h0, h1;
            h0.x = pk2(a.x, a.y); h0.y = pk2(a.z, a.w);
            h0.z = pk2(b.x, b.y); h0.w = pk2(b.z, b.w);
            h1.x = pk2(c.x, c.y); h1.y = pk2(c.z, c.w);
            h1.z = pk2(d.x, d.y); h1.w = pk2(d.z, d.w);
            *(uint4*)(st + aOff[p][0]) = h0;
            *(uint4*)(st + aOff[p][1]) = h1;
        }
    };
    auto cpB = [&](int s, int kt) {
        const uint32_t st = sb + s * STG + 16384;
        const int k0 = kt * KT;
        #pragma unroll
        for (int q8 = 0; q8 < 8; q8++) {
            int e = q8 * 256 + tid;
            int r = e >> 3, c = e & 7;
            cp16(st + soff64(r, c), g_Xhi + (size_t)r * K_ + k0 + c * 8);
        }
        cp_commit();
    };

    // prologue: stages 0 and 1
    ldgA(0); cpB(0, 0); stsA(0);
    ldgA(1); cpB(1, 1); stsA(1);

    for (int t = 0; t < NT1; t++) {
        const int pf = (t + 2 < NT1);
        if (pf) ldgA(t + 2);            // LDG early; STS after compute
        if (pf) cp_wait1(); else cp_wait0();
        __syncthreads();
        const int sNew = (t + 2) % NSTG;
        if (pf) cpB(sNew, t + 2);

        const uint32_t stA = sb + (t % NSTG) * STG;
        const uint32_t stB = stA + 16384;
        #pragma unroll
        for (int ks = 0; ks < 4; ks++) {
            const uint32_t cc = ks * 2 + (lane >> 4);
            uint32_t ah[4][4];
            #pragma unroll
            for (int mi = 0; mi < 4; mi++)
                ldsm4(ah[mi], stA + soff64(wm + mi * 16 + (lane & 15), cc));
            #pragma unroll
            for (int g = 0; g < 4; g++) {
                uint32_t bh[4];
                ldsm4(bh, stB + soff64(wn + g * 16 + (lane & 15), cc));
                #pragma unroll
                for (int mi = 0; mi < 4; mi++) {
                    mma_bf16(acc[mi][g*2],   ah[mi], bh[0], bh[2]);
                    mma_bf16(acc[mi][g*2+1], ah[mi], bh[1], bh[3]);
                }
            }
        }
        if (pf) stsA(sNew);
    }

    // epilogue: scale, store bf16 scores, per-n maxima
    float mv0[8], mv1[8];
    #pragma unroll
    for (int mi = 0; mi < 4; mi++) {
        int m = m0 + wm + mi * 16 + (lane >> 2);
        #pragma unroll
        for (int nj = 0; nj < 8; nj++) {
            int n = wn + nj * 8 + (lane & 3) * 2;
            float v0 = acc[mi][nj][0] * INV_VAR, v1 = acc[mi][nj][1] * INV_VAR;
            float v2 = acc[mi][nj][2] * INV_VAR, v3 = acc[mi][nj][3] * INV_VAR;
            acc[mi][nj][0] = v0; acc[mi][nj][1] = v1;
            acc[mi][nj][2] = v2; acc[mi][nj][3] = v3;
            if (m < M_)     *(uint32_t*)&g_scores[(size_t)m * N_ + n]       = pk2(v0, v1);
            if (m + 8 < M_) *(uint32_t*)&g_scores[(size_t)(m + 8) * N_ + n] = pk2(v2, v3);
        }
    }
    #pragma unroll
    for (int nj = 0; nj < 8; nj++) {
        float v0 = -1e30f, v1 = -1e30f;
        #pragma unroll
        for (int mi = 0; mi < 4; mi++) {
            v0 = fmaxf(v0, fmaxf(acc[mi][nj][0], acc[mi][nj][2]));
            v1 = fmaxf(v1, fmaxf(acc[mi][nj][1], acc[mi][nj][3]));
        }
        #pragma unroll
        for (int mk = 4; mk < 32; mk <<= 1) {
            v0 = fmaxf(v0, __shfl_xor_sync(0xFFFFFFFFu, v0, mk));
            v1 = fmaxf(v1, __shfl_xor_sync(0xFFFFFFFFu, v1, mk));
        }
        mv0[nj] = v0; mv1[nj] = v1;
    }
    float* s_max = (float*)smem;          // stage-0 A region dead after final barrier
    __syncthreads();
    if (wm == 0 && (lane >> 2) == 0) {
        #pragma unroll
        for (int nj = 0; nj < 8; nj++) {
            int n = wn + nj * 8 + (lane & 3) * 2;
            s_max[n] = mv0[nj]; s_max[n + 1] = mv1[nj];
        }
    }
    __syncthreads();
    if (wm == 64 && (lane >> 2) == 0) {
        #pragma unroll
        for (int nj = 0; nj < 8; nj++) {
            int n = wn + nj * 8 + (lane & 3) * 2;
            float c0 = fmaxf(mv0[nj], s_max[n]);
            float c1 = fmaxf(mv1[nj], s_max[n + 1]);
            g_tmax[(size_t)blockIdx.x * N_ + n]     = c0;
            g_tmax[(size_t)blockIdx.x * N_ + n + 1] = c1;
            atomicMax(&g_gmax_u[n],     fkey(c0));
            atomicMax(&g_gmax_u[n + 1], fkey(c1));
        }
    }
}

// ---------------- select (bf16 approx scores, widened margin) ----------------
__global__ __launch_bounds__(256)
void k_select() {
    __shared__ int s_list[LMAX];
    __shared__ int s_nlist, s_cnt;
    const int n = blockIdx.x, tid = threadIdx.x;
    if (tid == 0) { s_nlist = 0; s_cnt = 0; }
    __syncthreads();
    const float thr = funkey(g_gmax_u[n]) - THRESH;
    for (int b = tid; b < NTILE; b += 256) {
        if (g_tmax[(size_t)b * N_ + n] > thr) {
            int s = atomicAdd(&s_nlist, 1);
            if (s < LMAX) s_list[s] = b;
        }
    }
    __syncthreads();
    int nlist = s_nlist; if (nlist > LMAX) nlist = LMAX;
    const int nrows = nlist * 128;
    for (int r = tid; r < nrows; r += 256) {
        int m = s_list[r >> 7] * 128 + (r & 127);
        if (m < M_) {
            if (__bfloat162float(g_scores[(size_t)m * N_ + n]) > thr) {
                int s = atomicAdd(&s_cnt, 1);
                if (s < HMAX) g_hit_m[n * HMAX + s] = m;
            }
        }
    }
    __syncthreads();
    if (tid == 0) g_cnt[n] = s_cnt;
}

// ---------------- out: exact fp32 scores for candidates, exact softmax -------
__global__ __launch_bounds__(256)
void k_out(const float* __restrict__ X, const float* __restrict__ D,
           float* __restrict__ out) {
    __shared__ int   hm[HMAX];
    __shared__ float s_sc[HMAX];
    __shared__ float hw[HMAX];
    __shared__ float red[256];
    const int n = blockIdx.x, tid = threadIdx.x;
    int cnt = g_cnt[n]; if (cnt > HMAX) cnt = HMAX;
    if (tid < cnt) hm[tid] = g_hit_m[n * HMAX + tid];
    __syncthreads();
    if (tid == 0) {            // sort by m -> deterministic everything below
        for (int i = 1; i < cnt; i++) {
            int km = hm[i]; int j = i - 1;
            while (j >= 0 && hm[j] > km) { hm[j+1] = hm[j]; j--; }
            hm[j+1] = km;
        }
    }
    __syncthreads();

    float xr[12];
    #pragma unroll
    for (int q = 0; q < 12; q++) xr[q] = X[(size_t)n * K_ + tid + q * 256];

    for (int l = 0; l < cnt; l++) {
        const float* dr = D + (size_t)hm[l] * K_;
        float p = 0.f;
        #pragma unroll
        for (int q = 0; q < 12; q++) p += xr[q] * dr[tid + q * 256];
        red[tid] = p; __syncthreads();
        #pragma unroll
        for (int off = 128; off > 0; off >>= 1) {
            if (tid < off) red[tid] += red[tid + off];
            __syncthreads();
        }
        if (tid == 0) s_sc[l] = red[0] * INV_VAR;
        __syncthreads();
    }

    float gm = -1e30f;
    for (int l = 0; l < cnt; l++) gm = fmaxf(gm, s_sc[l]);
    if (tid < cnt) hw[tid] = expf(s_sc[tid] - gm);
    __syncthreads();
    float wsum = 0.f;
    for (int l = 0; l < cnt; l++) wsum += hw[l];
    const float inv = 1.0f / wsum;

    #pragma unroll
    for (int q = 0; q < 12; q++) {
        int j = tid + q * 256;
        float a = 0.f;
        for (int l = 0; l < cnt; l++)
            a += hw[l] * D[(size_t)hm[l] * K_ + j];
        out[(size_t)n * K_ + j] = a * inv;
    }
}

// ---------------- launch ----------------
extern "C" void kernel_launch(void* const* d_in, const int* in_sizes, int n_in,
                              void* d_out, int out_size) {
    (void)in_sizes; (void)n_in; (void)out_size;
    const float* X = (const float*)d_in[0];
    const float* D = (const float*)d_in[1];
    float* out = (float*)d_out;

    cudaFuncSetAttribute(k_gemm1, cudaFuncAttributeMaxDynamicSharedMemorySize, NSTG * STG);

    k_split_x<<<(N_ * K_ / 4 + 255) / 256, 256>>>(X);

    k_gemm1<<<(M_ + 127) / 128, 256, NSTG * STG>>>(D);

    k_select<<<N_, 256>>>();
    k_out<<<N_, 256>>>(X, D, out);
}

// round 12
// speedup vs baseline: 3.3849x; 1.1047x over previous
#include <cuda_runtime.h>
#include <cuda_bf16.h>
#include <math.h>
#include <stdint.h>

#define N_     256
#define M_     50000
#define K_     3072
#define KT     64             // bf16 k per tile (128B rows, classic SW128)
#define NT1    (K_ / KT)      // 48
#define NTILE  391            // ceil(M/128)
#define INV_VAR 4.0f
#define HMAX   64
#define LMAX   64
#define THRESH 38.0f          // 30 (softmax support) + 8 (bf16 score + bf16 store margin)
#define STG    49152          // stage: A 16K | B 32K
#define NSTG   3

// ---------------- device scratch (allocation-free) ----------------
__device__ __align__(128) __nv_bfloat16  g_scores[(size_t)M_ * N_];
__device__ __align__(128) __nv_bfloat16  g_Xhi[(size_t)N_ * K_];
__device__ __align__(128) float          g_tmax[(size_t)NTILE * N_];
__device__ unsigned int g_gmax_u[N_];

// ---------------- helpers ----------------
__device__ __forceinline__ uint32_t s2u(const void* p) {
    return (uint32_t)__cvta_generic_to_shared(p);
}
// 128B rows, classic SW128: chunk c (16B) XOR row&7
__device__ __forceinline__ uint32_t soff64(uint32_t r, uint32_t c) {
    return (r << 7) + ((c ^ (r & 7)) << 4);
}
__device__ __forceinline__ void cp16(uint32_t dst, const void* src) {
    asm volatile("cp.async.cg.shared.global [%0], [%1], 16;" :: "r"(dst), "l"(src));
}
__device__ __forceinline__ void cp_commit() { asm volatile("cp.async.commit_group;"); }
__device__ __forceinline__ void cp_wait1() { asm volatile("cp.async.wait_group 1;" ::: "memory"); }
__device__ __forceinline__ void cp_wait0() { asm volatile("cp.async.wait_group 0;" ::: "memory"); }

__device__ __forceinline__ void ldsm4(uint32_t* d, uint32_t addr) {
    asm volatile("ldmatrix.sync.aligned.m8n8.x4.shared.b16 {%0,%1,%2,%3}, [%4];"
        : "=r"(d[0]), "=r"(d[1]), "=r"(d[2]), "=r"(d[3]) : "r"(addr));
}
__device__ __forceinline__ void mma_bf16(float* c, const uint32_t* a, uint32_t b0, uint32_t b1) {
    asm volatile("mma.sync.aligned.m16n8k16.row.col.f32.bf16.bf16.f32 "
        "{%0,%1,%2,%3}, {%4,%5,%6,%7}, {%8,%9}, {%0,%1,%2,%3};"
        : "+f"(c[0]), "+f"(c[1]), "+f"(c[2]), "+f"(c[3])
        : "r"(a[0]), "r"(a[1]), "r"(a[2]), "r"(a[3]), "r"(b0), "r"(b1));
}
__device__ __forceinline__ unsigned int fkey(float f) {
    unsigned int b = __float_as_uint(f);
    return (b & 0x80000000u) ? ~b : (b | 0x80000000u);
}
__device__ __forceinline__ float funkey(unsigned int k) {
    unsigned int b = (k & 0x80000000u) ? (k & 0x7FFFFFFFu) : ~k;
    return __uint_as_float(b);
}
__device__ __forceinline__ uint32_t pk2(float x, float y) {   // bf16(x) low, bf16(y) high
    __nv_bfloat162 t = __floats2bfloat162_rn(x, y);
    return *(uint32_t*)&t;
}

// ---------------- X fp32 -> bf16 (+ zero per-launch state in block 0) --------
__global__ __launch_bounds__(256)
void k_split_x(const float* __restrict__ X) {
    if (blockIdx.x == 0) g_gmax_u[threadIdx.x] = 0u;
    size_t i = (size_t)blockIdx.x * 256 + threadIdx.x;
    if (i >= (size_t)N_ * K_ / 4) return;
    float4 v = ((const float4*)X)[i];
    unsigned long long ph = (unsigned long long)pk2(v.x, v.y)
                          | ((unsigned long long)pk2(v.z, v.w) << 32);
    ((unsigned long long*)g_Xhi)[i] = ph;
}

// ---------------- GEMM1: approx scores[m][n] = 4 * bf16(D).bf16(X)^T ---------
// CTA tile 128m x 256n. 8 warps = 2m x 4n, warp tile 64x64. KT=64, 3-stage
// ring, prefetch distance 2. D read once (fp32), converted in-register.
__global__ __launch_bounds__(256, 1)
void k_gemm1(const float* __restrict__ Dp) {
    extern __shared__ char smem[];
    const uint32_t sb = s2u(smem);
    const int tid = threadIdx.x, wid = tid >> 5, lane = tid & 31;
    const int m0 = blockIdx.x * 128;
    const int wm = (wid >> 2) * 64;        // 0 or 64
    const int wn = (wid & 3) * 64;         // 0,64,128,192

    const float* aPtr[2];
    uint32_t aOff[2][2];
    #pragma unroll
    for (int p = 0; p < 2; p++) {
        int e = tid + p * 256;
        int row = e >> 2, q = e & 3;
        int m = m0 + row; if (m >= M_) m = M_ - 1;
        aPtr[p] = Dp + (size_t)m * K_ + q * 16;
        aOff[p][0] = soff64(row, q * 2);
        aOff[p][1] = soff64(row, q * 2 + 1);
    }

    float acc[4][8][4];
    #pragma unroll
    for (int a = 0; a < 4; a++)
        #pragma unroll
        for (int b = 0; b < 8; b++)
            #pragma unroll
            for (int q = 0; q < 4; q++) acc[a][b][q] = 0.f;

    float4 fA[8];
    auto ldgA = [&](int kt) {
        #pragma unroll
        for (int p = 0; p < 2; p++) {
            const float* ptr = aPtr[p] + kt * KT;
            fA[p*4+0] = *(const float4*)(ptr);
            fA[p*4+1] = *(const float4*)(ptr + 4);
            fA[p*4+2] = *(const float4*)(ptr + 8);
            fA[p*4+3] = *(const float4*)(ptr + 12);
        }
    };
    auto stsA = [&](int s) {
        char* st = smem + s * STG;
        #pragma unroll
        for (int p = 0; p < 2; p++) {
            float4 a = fA[p*4+0], b = fA[p*4+1], c = fA[p*4+2], d = fA[p*4+3];
            uint4 h0, h1;
            h0.x = pk2(a.x, a.y); h0.y = pk2(a.z, a.w);
            h0.z = pk2(b.x, b.y); h0.w = pk2(b.z, b.w);
            h1.x = pk2(c.x, c.y); h1.y = pk2(c.z, c.w);
            h1.z = pk2(d.x, d.y); h1.w = pk2(d.z, d.w);
            *(uint4*)(st + aOff[p][0]) = h0;
            *(uint4*)(st + aOff[p][1]) = h1;
        }
    };
    auto cpB = [&](int s, int kt) {
        const uint32_t st = sb + s * STG + 16384;
        const int k0 = kt * KT;
        #pragma unroll
        for (int q8 = 0; q8 < 8; q8++) {
            int e = q8 * 256 + tid;
            int r = e >> 3, c = e & 7;
            cp16(st + soff64(r, c), g_Xhi + (size_t)r * K_ + k0 + c * 8);
        }
        cp_commit();
    };

    ldgA(0); cpB(0, 0); stsA(0);
    ldgA(1); cpB(1, 1); stsA(1);

    for (int t = 0; t < NT1; t++) {
        const int pf = (t + 2 < NT1);
        if (pf) ldgA(t + 2);
        if (pf) cp_wait1(); else cp_wait0();
        __syncthreads();
        const int sNew = (t + 2) % NSTG;
        if (pf) cpB(sNew, t + 2);

        const uint32_t stA = sb + (t % NSTG) * STG;
        const uint32_t stB = stA + 16384;
        #pragma unroll
        for (int ks = 0; ks < 4; ks++) {
            const uint32_t cc = ks * 2 + (lane >> 4);
            uint32_t ah[4][4];
            #pragma unroll
            for (int mi = 0; mi < 4; mi++)
                ldsm4(ah[mi], stA + soff64(wm + mi * 16 + (lane & 15), cc));
            #pragma unroll
            for (int g = 0; g < 4; g++) {
                uint32_t bh[4];
                ldsm4(bh, stB + soff64(wn + g * 16 + (lane & 15), cc));
                #pragma unroll
                for (int mi = 0; mi < 4; mi++) {
                    mma_bf16(acc[mi][g*2],   ah[mi], bh[0], bh[2]);
                    mma_bf16(acc[mi][g*2+1], ah[mi], bh[1], bh[3]);
                }
            }
        }
        if (pf) stsA(sNew);
    }

    // epilogue: scale, store bf16 scores, per-n maxima
    float mv0[8], mv1[8];
    #pragma unroll
    for (int mi = 0; mi < 4; mi++) {
        int m = m0 + wm + mi * 16 + (lane >> 2);
        #pragma unroll
        for (int nj = 0; nj < 8; nj++) {
            int n = wn + nj * 8 + (lane & 3) * 2;
            float v0 = acc[mi][nj][0] * INV_VAR, v1 = acc[mi][nj][1] * INV_VAR;
            float v2 = acc[mi][nj][2] * INV_VAR, v3 = acc[mi][nj][3] * INV_VAR;
            acc[mi][nj][0] = v0; acc[mi][nj][1] = v1;
            acc[mi][nj][2] = v2; acc[mi][nj][3] = v3;
            if (m < M_)     *(uint32_t*)&g_scores[(size_t)m * N_ + n]       = pk2(v0, v1);
            if (m + 8 < M_) *(uint32_t*)&g_scores[(size_t)(m + 8) * N_ + n] = pk2(v2, v3);
        }
    }
    #pragma unroll
    for (int nj = 0; nj < 8; nj++) {
        float v0 = -1e30f, v1 = -1e30f;
        #pragma unroll
        for (int mi = 0; mi < 4; mi++) {
            v0 = fmaxf(v0, fmaxf(acc[mi][nj][0], acc[mi][nj][2]));
            v1 = fmaxf(v1, fmaxf(acc[mi][nj][1], acc[mi][nj][3]));
        }
        #pragma unroll
        for (int mk = 4; mk < 32; mk <<= 1) {
            v0 = fmaxf(v0, __shfl_xor_sync(0xFFFFFFFFu, v0, mk));
            v1 = fmaxf(v1, __shfl_xor_sync(0xFFFFFFFFu, v1, mk));
        }
        mv0[nj] = v0; mv1[nj] = v1;
    }
    float* s_max = (float*)smem;          // stage-0 A region dead after final barrier
    __syncthreads();
    if (wm == 0 && (lane >> 2) == 0) {
        #pragma unroll
        for (int nj = 0; nj < 8; nj++) {
            int n = wn + nj * 8 + (lane & 3) * 2;
            s_max[n] = mv0[nj]; s_max[n + 1] = mv1[nj];
        }
    }
    __syncthreads();
    if (wm == 64 && (lane >> 2) == 0) {
        #pragma unroll
        for (int nj = 0; nj < 8; nj++) {
            int n = wn + nj * 8 + (lane & 3) * 2;
            float c0 = fmaxf(mv0[nj], s_max[n]);
            float c1 = fmaxf(mv1[nj], s_max[n + 1]);
            g_tmax[(size_t)blockIdx.x * N_ + n]     = c0;
            g_tmax[(size_t)blockIdx.x * N_ + n + 1] = c1;
            atomicMax(&g_gmax_u[n],     fkey(c0));
            atomicMax(&g_gmax_u[n + 1], fkey(c1));
        }
    }
}

// ---------------- fused select + exact rescore + output ----------------------
// One CTA per n. Select from bf16 approx scores (hierarchical), sort hits,
// recompute exact fp32 scores warp-per-candidate, exact softmax, output.
__global__ __launch_bounds__(256)
void k_out(const float* __restrict__ X, const float* __restrict__ D,
           float* __restrict__ out) {
    __shared__ int   s_list[LMAX];
    __shared__ int   hm[HMAX];
    __shared__ float s_sc[HMAX];
    __shared__ float hw[HMAX];
    __shared__ int   s_nlist, s_cnt;
    const int n = blockIdx.x, tid = threadIdx.x;
    const int wid = tid >> 5, lane = tid & 31;

    if (tid == 0) { s_nlist = 0; s_cnt = 0; }
    __syncthreads();
    const float thr = funkey(g_gmax_u[n]) - THRESH;

    // phase 1: hot tiles
    for (int b = tid; b < NTILE; b += 256) {
        if (g_tmax[(size_t)b * N_ + n] > thr) {
            int s = atomicAdd(&s_nlist, 1);
            if (s < LMAX) s_list[s] = b;
        }
    }
    __syncthreads();
    int nlist = s_nlist; if (nlist > LMAX) nlist = LMAX;

    // phase 2: rows of hot tiles, one load per thread
    const int nrows = nlist * 128;
    for (int r = tid; r < nrows; r += 256) {
        int m = s_list[r >> 7] * 128 + (r & 127);
        if (m < M_) {
            if (__bfloat162float(g_scores[(size_t)m * N_ + n]) > thr) {
                int s = atomicAdd(&s_cnt, 1);
                if (s < HMAX) hm[s] = m;
            }
        }
    }
    __syncthreads();
    int cnt = s_cnt; if (cnt > HMAX) cnt = HMAX;

    // sort by m -> deterministic order for everything below
    if (tid == 0) {
        for (int i = 1; i < cnt; i++) {
            int km = hm[i]; int j = i - 1;
            while (j >= 0 && hm[j] > km) { hm[j+1] = hm[j]; j--; }
            hm[j+1] = km;
        }
    }
    __syncthreads();

    // phase 3: exact fp32 scores, one warp per candidate (fixed-tree shuffle)
    const float* xp = X + (size_t)n * K_;
    for (int l = wid; l < cnt; l += 8) {
        const float* dr = D + (size_t)hm[l] * K_;
        float p = 0.f;
        #pragma unroll
        for (int q = 0; q < K_ / 32; q++)
            p += xp[lane + q * 32] * dr[lane + q * 32];
        #pragma unroll
        for (int mk = 16; mk > 0; mk >>= 1)
            p += __shfl_xor_sync(0xFFFFFFFFu, p, mk);
        if (lane == 0) s_sc[l] = p * INV_VAR;
    }
    __syncthreads();

    // phase 4: exact softmax over candidates
    float gm = -1e30f;
    for (int l = 0; l < cnt; l++) gm = fmaxf(gm, s_sc[l]);
    if (tid < cnt) hw[tid] = expf(s_sc[tid] - gm);
    __syncthreads();
    float wsum = 0.f;
    for (int l = 0; l < cnt; l++) wsum += hw[l];
    const float inv = 1.0f / wsum;

    // phase 5: output (D rows L2-hot from phase 3)
    #pragma unroll
    for (int q = 0; q < 12; q++) {
        int j = tid + q * 256;
        float a = 0.f;
        for (int l = 0; l < cnt; l++)
            a += hw[l] * D[(size_t)hm[l] * K_ + j];
        out[(size_t)n * K_ + j] = a * inv;
    }
}

// ---------------- launch ----------------
extern "C" void kernel_launch(void* const* d_in, const int* in_sizes, int n_in,
                              void* d_out, int out_size) {
    (void)in_sizes; (void)n_in; (void)out_size;
    const float* X = (const float*)d_in[0];
    const float* D = (const float*)d_in[1];
    float* out = (float*)d_out;

    cudaFuncSetAttribute(k_gemm1, cudaFuncAttributeMaxDynamicSharedMemorySize, NSTG * STG);

    k_split_x<<<(N_ * K_ / 4 + 255) / 256, 256>>>(X);

    k_gemm1<<<(M_ + 127) / 128, 256, NSTG * STG>>>(D);

    k_out<<<N_, 256>>>(X, D, out);
}